// round 4
// baseline (speedup 1.0000x reference)
#include <cuda_runtime.h>

#define B_   1024
#define T_   512
#define F_   32
#define E_   16
#define H_   128
#define G_   384      // 3*H
#define KX_  48       // F + E
#define ROWS 8        // batch rows per block
#define NBLK (B_/ROWS)  // 128 blocks
#define NTHR 512      // tid = 4*j + kq : 128 units x 4 k-quarters

typedef unsigned long long u64;

// Quad-packed transposed weights: layout [k/4][g][4]
__device__ __align__(16) float Wq_ih0[KX_*G_];
__device__ __align__(16) float Wq_hh0[H_*G_];
__device__ __align__(16) float Wq_ih1[H_*G_];
__device__ __align__(16) float Wq_hh1[H_*G_];

__global__ void prep_kernel(const float* __restrict__ W_ih0,
                            const float* __restrict__ W_hh0,
                            const float* __restrict__ W_ih1,
                            const float* __restrict__ W_hh1) {
    int idx = blockIdx.x * blockDim.x + threadIdx.x;
    if (idx < KX_ * G_) {
        int g = idx / KX_, k = idx % KX_;
        Wq_ih0[((k >> 2) * G_ + g) * 4 + (k & 3)] = W_ih0[idx];
    }
    if (idx < H_ * G_) {
        int g = idx / H_, k = idx % H_;
        int dst = ((k >> 2) * G_ + g) * 4 + (k & 3);
        Wq_hh0[dst] = W_hh0[idx];
        Wq_ih1[dst] = W_ih1[idx];
        Wq_hh1[dst] = W_hh1[idx];
    }
}

__device__ __forceinline__ u64 fma2(u64 a, u64 b, u64 c) {
    u64 d;
    asm("fma.rn.f32x2 %0, %1, %2, %3;" : "=l"(d) : "l"(a), "l"(b), "l"(c));
    return d;
}
__device__ __forceinline__ float hsum2(u64 a) {
    float l, h;
    asm("mov.b64 {%0, %1}, %2;" : "=f"(l), "=f"(h) : "l"(a));
    return l + h;
}
__device__ __forceinline__ ulonglong2 ldcg128(const float* p) {
    ulonglong2 v;
    asm("ld.global.cg.v2.u64 {%0, %1}, [%2];" : "=l"(v.x), "=l"(v.y) : "l"(p));
    return v;
}
__device__ __forceinline__ float sigmoidf_(float v) {
    return 1.f / (1.f + __expf(-v));
}
__device__ __forceinline__ float tanhf_(float v) {
    v = fminf(fmaxf(v, -15.f), 15.f);
    float e = __expf(2.f * v);
    return (e - 1.f) / (e + 1.f);
}

__global__ void __launch_bounds__(NTHR, 1) gru_kernel(
    const float* __restrict__ x,         // (B, T, F)
    const int*   __restrict__ ticker,    // (B,)
    const float* __restrict__ embed,     // (N_TICKERS, E)
    const float* __restrict__ b_ih0, const float* __restrict__ b_hh0,
    const float* __restrict__ b_ih1, const float* __restrict__ b_hh1,
    const float* __restrict__ head_w1, const float* __restrict__ head_b1,
    const float* __restrict__ head_w2, const float* __restrict__ head_b2,
    float* __restrict__ y)               // (B,)
{
    extern __shared__ float sm[];
    float* Wh1 = sm;                       // H_*G_ floats (192KB): W_hh1 parked
    float* h0b = sm + H_ * G_;             // 2 * ROWS*H_   (double buffer)
    float* h1b = h0b + 2 * ROWS * H_;      // 2 * ROWS*H_
    float* xeb = h1b + 2 * ROWS * H_;      // 2 * ROWS*KX_

    const int tid = threadIdx.x;
    const int j   = tid >> 2;              // hidden unit 0..127
    const int kq  = tid & 3;               // k-quarter
    const int b0  = blockIdx.x * ROWS;
    const int row0 = 2 * kq;               // rows this thread finalizes

    // park W_hh1 in SMEM (quad layout preserved)
    {
        const float4* src = (const float4*)Wq_hh1;
        float4* dst = (float4*)Wh1;
        for (int i = tid; i < H_ * G_ / 4; i += NTHR) dst[i] = src[i];
    }
    for (int i = tid; i < 2 * ROWS * H_; i += NTHR) { h0b[i] = 0.f; h1b[i] = 0.f; }
    // embedding into BOTH x buffers (constant over t)
    if (tid < ROWS * E_) {
        int r = tid / E_, e = tid % E_;
        float v = embed[(size_t)ticker[b0 + r] * E_ + e];
        xeb[r * KX_ + F_ + e] = v;
        xeb[ROWS * KX_ + r * KX_ + F_ + e] = v;
    }
    // stage x for t = 0 into buffer 0
    if (tid < ROWS * F_) {
        int r = tid >> 5, c = tid & 31;
        xeb[r * KX_ + c] = x[((size_t)(b0 + r) * T_) * F_ + c];
    }

    const float br0  = b_ih0[j]        + b_hh0[j];
    const float bz0  = b_ih0[H_ + j]   + b_hh0[H_ + j];
    const float bxn0 = b_ih0[2*H_ + j];
    const float bhn0 = b_hh0[2*H_ + j];
    const float br1  = b_ih1[j]        + b_hh1[j];
    const float bz1  = b_ih1[H_ + j]   + b_hh1[H_ + j];
    const float bxn1 = b_ih1[2*H_ + j];
    const float bhn1 = b_hh1[2*H_ + j];

    // weight bases: quad layout (kquad*G_ + g)*4 floats; gate offsets are
    // compile-time immediates (+H_*4, +2*H_*4 floats).
    const float* pih0 = Wq_ih0 + ((size_t)(kq * 3) * G_ + j) * 4;
    const float* phh0 = Wq_hh0 + ((size_t)(kq * 8) * G_ + j) * 4;
    const float* pih1 = Wq_ih1 + ((size_t)(kq * 8) * G_ + j) * 4;
    const float* pwh1 = Wh1    + ((size_t)(kq * 8) * G_ + j) * 4;

    const bool hiK = (kq & 2);             // which row-half I keep at stage 1
    const bool hiP = (kq & 1);             // which row-pair I keep at stage 2

    float h0r[2] = {0.f, 0.f}, h1r[2] = {0.f, 0.f};

    __syncthreads();

    for (int t = 0; t < T_; ++t) {
        const float* xcur  = xeb + (t & 1) * ROWS * KX_;
        const float* h0old = h0b + (t & 1) * ROWS * H_;
        float*       h0new = h0b + ((t + 1) & 1) * ROWS * H_;
        const float* h1old = h1b + (t & 1) * ROWS * H_;
        float*       h1new = h1b + ((t + 1) & 1) * ROWS * H_;

        u64 ar[ROWS], az[ROWS], an[ROWS];
        float xnf[ROWS];

        // ================= layer 0 =================
#pragma unroll
        for (int r = 0; r < ROWS; r++) { ar[r] = 0; az[r] = 0; an[r] = 0; }
        // ih part: 3 quads of xcat (this k-quarter)
#pragma unroll
        for (int kk = 0; kk < 3; ++kk) {
            ulonglong2 wr = ldcg128(pih0 + (size_t)kk * G_ * 4);
            ulonglong2 wz = ldcg128(pih0 + (size_t)kk * G_ * 4 + H_ * 4);
            ulonglong2 wn = ldcg128(pih0 + (size_t)kk * G_ * 4 + 2 * H_ * 4);
#pragma unroll
            for (int r = 0; r < ROWS; r++) {
                ulonglong2 v = *(const ulonglong2*)(xcur + r * KX_ + kq * 12 + kk * 4);
                ar[r] = fma2(wr.x, v.x, ar[r]); ar[r] = fma2(wr.y, v.y, ar[r]);
                az[r] = fma2(wz.x, v.x, az[r]); az[r] = fma2(wz.y, v.y, az[r]);
                an[r] = fma2(wn.x, v.x, an[r]); an[r] = fma2(wn.y, v.y, an[r]);
            }
        }
#pragma unroll
        for (int r = 0; r < ROWS; r++) { xnf[r] = hsum2(an[r]); an[r] = 0; }
        // hh part: 8 quads of h0old
#pragma unroll
        for (int kk = 0; kk < 8; ++kk) {
            ulonglong2 wr = ldcg128(phh0 + (size_t)kk * G_ * 4);
            ulonglong2 wz = ldcg128(phh0 + (size_t)kk * G_ * 4 + H_ * 4);
            ulonglong2 wn = ldcg128(phh0 + (size_t)kk * G_ * 4 + 2 * H_ * 4);
#pragma unroll
            for (int r = 0; r < ROWS; r++) {
                ulonglong2 v = *(const ulonglong2*)(h0old + r * H_ + kq * 32 + kk * 4);
                ar[r] = fma2(wr.x, v.x, ar[r]); ar[r] = fma2(wr.y, v.y, ar[r]);
                az[r] = fma2(wz.x, v.x, az[r]); az[r] = fma2(wz.y, v.y, az[r]);
                an[r] = fma2(wn.x, v.x, an[r]); an[r] = fma2(wn.y, v.y, an[r]);
            }
        }
        // ---- cross-k reduce (shfl butterfly within 4-lane group) + finalize
        {
            float vr[ROWS], vz[ROWS], vh[ROWS];
#pragma unroll
            for (int r = 0; r < ROWS; r++) {
                vr[r] = hsum2(ar[r]); vz[r] = hsum2(az[r]); vh[r] = hsum2(an[r]);
            }
            float kr[4], kz[4], kx[4], kh[4];
#pragma unroll
            for (int rr = 0; rr < 4; ++rr) {
                float sr = hiK ? vr[rr] : vr[4+rr];
                float cr = hiK ? vr[4+rr] : vr[rr];
                kr[rr] = cr + __shfl_xor_sync(0xffffffffu, sr, 2, 4);
                float sz = hiK ? vz[rr] : vz[4+rr];
                float cz = hiK ? vz[4+rr] : vz[rr];
                kz[rr] = cz + __shfl_xor_sync(0xffffffffu, sz, 2, 4);
                float sx = hiK ? xnf[rr] : xnf[4+rr];
                float cx = hiK ? xnf[4+rr] : xnf[rr];
                kx[rr] = cx + __shfl_xor_sync(0xffffffffu, sx, 2, 4);
                float sh = hiK ? vh[rr] : vh[4+rr];
                float ch = hiK ? vh[4+rr] : vh[rr];
                kh[rr] = ch + __shfl_xor_sync(0xffffffffu, sh, 2, 4);
            }
#pragma unroll
            for (int rr = 0; rr < 2; ++rr) {
                float sr = hiP ? kr[rr] : kr[2+rr];
                float cr = hiP ? kr[2+rr] : kr[rr];
                float fr = cr + __shfl_xor_sync(0xffffffffu, sr, 1, 4);
                float sz = hiP ? kz[rr] : kz[2+rr];
                float cz = hiP ? kz[2+rr] : kz[rr];
                float fz = cz + __shfl_xor_sync(0xffffffffu, sz, 1, 4);
                float sx = hiP ? kx[rr] : kx[2+rr];
                float cx = hiP ? kx[2+rr] : kx[rr];
                float fx = cx + __shfl_xor_sync(0xffffffffu, sx, 1, 4);
                float sh = hiP ? kh[rr] : kh[2+rr];
                float ch = hiP ? kh[2+rr] : kh[rr];
                float fh = ch + __shfl_xor_sync(0xffffffffu, sh, 1, 4);

                float R = sigmoidf_(fr + br0);
                float Z = sigmoidf_(fz + bz0);
                float N = tanhf_(fx + bxn0 + R * (fh + bhn0));
                float h = N + Z * (h0r[rr] - N);
                h0r[rr] = h;
                h0new[(row0 + rr) * H_ + j] = h;
            }
        }
        __syncthreads();   // h0(t) published

        // ================= layer 1 =================
#pragma unroll
        for (int r = 0; r < ROWS; r++) { ar[r] = 0; az[r] = 0; an[r] = 0; }
        // ih part: 8 quads of h0new (W_ih1 streamed)
#pragma unroll
        for (int kk = 0; kk < 8; ++kk) {
            ulonglong2 wr = ldcg128(pih1 + (size_t)kk * G_ * 4);
            ulonglong2 wz = ldcg128(pih1 + (size_t)kk * G_ * 4 + H_ * 4);
            ulonglong2 wn = ldcg128(pih1 + (size_t)kk * G_ * 4 + 2 * H_ * 4);
#pragma unroll
            for (int r = 0; r < ROWS; r++) {
                ulonglong2 v = *(const ulonglong2*)(h0new + r * H_ + kq * 32 + kk * 4);
                ar[r] = fma2(wr.x, v.x, ar[r]); ar[r] = fma2(wr.y, v.y, ar[r]);
                az[r] = fma2(wz.x, v.x, az[r]); az[r] = fma2(wz.y, v.y, az[r]);
                an[r] = fma2(wn.x, v.x, an[r]); an[r] = fma2(wn.y, v.y, an[r]);
            }
        }
#pragma unroll
        for (int r = 0; r < ROWS; r++) { xnf[r] = hsum2(an[r]); an[r] = 0; }
        // hh part: 8 quads of h1old (W_hh1 from SMEM)
#pragma unroll
        for (int kk = 0; kk < 8; ++kk) {
            ulonglong2 wr = *(const ulonglong2*)(pwh1 + (size_t)kk * G_ * 4);
            ulonglong2 wz = *(const ulonglong2*)(pwh1 + (size_t)kk * G_ * 4 + H_ * 4);
            ulonglong2 wn = *(const ulonglong2*)(pwh1 + (size_t)kk * G_ * 4 + 2 * H_ * 4);
#pragma unroll
            for (int r = 0; r < ROWS; r++) {
                ulonglong2 v = *(const ulonglong2*)(h1old + r * H_ + kq * 32 + kk * 4);
                ar[r] = fma2(wr.x, v.x, ar[r]); ar[r] = fma2(wr.y, v.y, ar[r]);
                az[r] = fma2(wz.x, v.x, az[r]); az[r] = fma2(wz.y, v.y, az[r]);
                an[r] = fma2(wn.x, v.x, an[r]); an[r] = fma2(wn.y, v.y, an[r]);
            }
        }
        {
            float vr[ROWS], vz[ROWS], vh[ROWS];
#pragma unroll
            for (int r = 0; r < ROWS; r++) {
                vr[r] = hsum2(ar[r]); vz[r] = hsum2(az[r]); vh[r] = hsum2(an[r]);
            }
            float kr[4], kz[4], kx[4], kh[4];
#pragma unroll
            for (int rr = 0; rr < 4; ++rr) {
                float sr = hiK ? vr[rr] : vr[4+rr];
                float cr = hiK ? vr[4+rr] : vr[rr];
                kr[rr] = cr + __shfl_xor_sync(0xffffffffu, sr, 2, 4);
                float sz = hiK ? vz[rr] : vz[4+rr];
                float cz = hiK ? vz[4+rr] : vz[rr];
                kz[rr] = cz + __shfl_xor_sync(0xffffffffu, sz, 2, 4);
                float sx = hiK ? xnf[rr] : xnf[4+rr];
                float cx = hiK ? xnf[4+rr] : xnf[rr];
                kx[rr] = cx + __shfl_xor_sync(0xffffffffu, sx, 2, 4);
                float sh = hiK ? vh[rr] : vh[4+rr];
                float ch = hiK ? vh[4+rr] : vh[rr];
                kh[rr] = ch + __shfl_xor_sync(0xffffffffu, sh, 2, 4);
            }
#pragma unroll
            for (int rr = 0; rr < 2; ++rr) {
                float sr = hiP ? kr[rr] : kr[2+rr];
                float cr = hiP ? kr[2+rr] : kr[rr];
                float fr = cr + __shfl_xor_sync(0xffffffffu, sr, 1, 4);
                float sz = hiP ? kz[rr] : kz[2+rr];
                float cz = hiP ? kz[2+rr] : kz[rr];
                float fz = cz + __shfl_xor_sync(0xffffffffu, sz, 1, 4);
                float sx = hiP ? kx[rr] : kx[2+rr];
                float cx = hiP ? kx[2+rr] : kx[rr];
                float fx = cx + __shfl_xor_sync(0xffffffffu, sx, 1, 4);
                float sh = hiP ? kh[rr] : kh[2+rr];
                float ch = hiP ? kh[2+rr] : kh[rr];
                float fh = ch + __shfl_xor_sync(0xffffffffu, sh, 1, 4);

                float R = sigmoidf_(fr + br1);
                float Z = sigmoidf_(fz + bz1);
                float N = tanhf_(fx + bxn1 + R * (fh + bhn1));
                float h = N + Z * (h1r[rr] - N);
                h1r[rr] = h;
                h1new[(row0 + rr) * H_ + j] = h;
            }
        }
        // stage x for t+1 into the other buffer (inside this barrier window)
        if (t + 1 < T_ && tid < ROWS * F_) {
            int r = tid >> 5, c = tid & 31;
            xeb[((t + 1) & 1) * ROWS * KX_ + r * KX_ + c] =
                x[((size_t)(b0 + r) * T_ + (t + 1)) * F_ + c];
        }
        __syncthreads();   // h1(t) + x(t+1) published
    }

    // ================= head =================
    // final h1 lives in buffer index (T_ & 1) == 0  → h1b base
    const float* hfin = h1b;
    float* scratch = h0b;                  // reuse as head scratch
    if (tid < H_) {
        const float w2  = head_w2[tid];
        const float b1v = head_b1[tid];
        float acc[ROWS];
#pragma unroll
        for (int r = 0; r < ROWS; r++) acc[r] = b1v;
        for (int k = 0; k < H_; k += 4) {
            float4 w = *(const float4*)(head_w1 + (size_t)tid * H_ + k);
#pragma unroll
            for (int r = 0; r < ROWS; r++) {
                float4 v = *(const float4*)(hfin + r * H_ + k);
                acc[r] += w.x * v.x + w.y * v.y + w.z * v.z + w.w * v.w;
            }
        }
#pragma unroll
        for (int r = 0; r < ROWS; r++)
            scratch[r * H_ + tid] = fmaxf(acc[r], 0.f) * w2;
    }
    __syncthreads();
    if (tid < ROWS) {
        float acc = head_b2[0];
        for (int k = 0; k < H_; k++) acc += scratch[tid * H_ + k];
        y[b0 + tid] = acc;
    }
}

extern "C" void kernel_launch(void* const* d_in, const int* in_sizes, int n_in,
                              void* d_out, int out_size) {
    const float* x       = (const float*)d_in[0];
    const int*   ticker  = (const int*)  d_in[1];
    const float* embed   = (const float*)d_in[2];
    const float* W_ih0   = (const float*)d_in[3];
    const float* W_hh0   = (const float*)d_in[4];
    const float* b_ih0   = (const float*)d_in[5];
    const float* b_hh0   = (const float*)d_in[6];
    const float* W_ih1   = (const float*)d_in[7];
    const float* W_hh1   = (const float*)d_in[8];
    const float* b_ih1   = (const float*)d_in[9];
    const float* b_hh1   = (const float*)d_in[10];
    const float* head_w1 = (const float*)d_in[11];
    const float* head_b1 = (const float*)d_in[12];
    const float* head_w2 = (const float*)d_in[13];
    const float* head_b2 = (const float*)d_in[14];

    const int smem_bytes = (H_ * G_ + 4 * ROWS * H_ + 2 * ROWS * KX_) * sizeof(float);
    cudaFuncSetAttribute(gru_kernel, cudaFuncAttributeMaxDynamicSharedMemorySize,
                         smem_bytes);

    prep_kernel<<<(H_ * G_ + 255) / 256, 256>>>(W_ih0, W_hh0, W_ih1, W_hh1);
    gru_kernel<<<NBLK, NTHR, smem_bytes>>>(x, ticker, embed,
                                           b_ih0, b_hh0, b_ih1, b_hh1,
                                           head_w1, head_b1, head_w2, head_b2,
                                           (float*)d_out);
}

// round 5
// speedup vs baseline: 1.6963x; 1.6963x over previous
#include <cuda_runtime.h>
#include <cstdint>

#define B_    1024
#define T_    512
#define F_    32
#define E_    16
#define H_    128
#define KX_   48          // F + E
#define CL_   4           // CTAs per cluster
#define UN_   32          // hidden units per CTA
#define GL_   96          // gate outputs per CTA (3 * UN_)
#define RWS_  32          // batch rows per cluster
#define NCTA  128         // 32 clusters * 4
#define NTHR  384         // tid = gl*4 + kq
#define HSTR  144         // padded h row stride (floats): 4 chunks of 36

typedef unsigned long long u64;

// ---------------- SMEM layout (floats) ----------------
#define OFF_WIH0   0                         // 96*48      = 4608
#define OFF_WHH0   (OFF_WIH0 + GL_*KX_)      // 96*128     = 12288
#define OFF_WIH1   (OFF_WHH0 + GL_*H_)
#define OFF_WHH1   (OFF_WIH1 + GL_*H_)
#define OFF_H0     (OFF_WHH1 + GL_*H_)       // 32*144     = 4608
#define OFF_H1     (OFF_H0 + RWS_*HSTR)
#define OFF_XS     (OFF_H1 + RWS_*HSTR)      // 32*48      = 1536
#define OFF_GBH    (OFF_XS + RWS_*KX_)       // 32*96      = 3072
#define OFF_GBX    (OFF_GBH + RWS_*GL_)      // 32*32      = 1024
#define OFF_BIAS   (OFF_GBX + RWS_*UN_)      // 8*32       = 256
#define SMEM_FLOATS (OFF_BIAS + 256)
#define SMEM_BYTES  (SMEM_FLOATS * 4)        // 226,304 B

// ---------------- helpers ----------------
__device__ __forceinline__ u64 fma2(u64 a, u64 b, u64 c) {
    u64 d;
    asm("fma.rn.f32x2 %0, %1, %2, %3;" : "=l"(d) : "l"(a), "l"(b), "l"(c));
    return d;
}
__device__ __forceinline__ float hsum2(u64 a) {
    float l, h;
    asm("mov.b64 {%0, %1}, %2;" : "=f"(l), "=f"(h) : "l"(a));
    return l + h;
}
__device__ __forceinline__ float sigmoidf_(float v) {
    return 1.f / (1.f + __expf(-v));
}
__device__ __forceinline__ float tanhf_(float v) {
    v = fminf(fmaxf(v, -15.f), 15.f);
    float e = __expf(2.f * v);
    return (e - 1.f) / (e + 1.f);
}
__device__ __forceinline__ uint32_t smem_u32(const void* p) {
    uint32_t a;
    asm("{ .reg .u64 t; cvta.to.shared.u64 t, %1; cvt.u32.u64 %0, t; }"
        : "=r"(a) : "l"(p));
    return a;
}
__device__ __forceinline__ void st_cluster_v2(uint32_t laddr, int rank,
                                              float a, float b) {
    asm volatile(
        "{ .reg .b32 ra;\n\t"
        "mapa.shared::cluster.u32 ra, %0, %1;\n\t"
        "st.shared::cluster.v2.f32 [ra], {%2, %3}; }"
        :: "r"(laddr), "r"(rank), "f"(a), "f"(b) : "memory");
}
#define CLUSTER_SYNC() do { \
    asm volatile("barrier.cluster.arrive.aligned;" ::: "memory"); \
    asm volatile("barrier.cluster.wait.aligned;"   ::: "memory"); \
} while (0)

// ---------------- per-layer gate compute ----------------
// Thread (gl, kq) accumulates its K-quarter of gate gl over 32 rows
// (4 blocks of 8), shfl-reduces across kq, writes finalized pre-activations
// for rows {rb*8+2kq, rb*8+2kq+1} into gb buffers.
template<int AQ, int AOFF, int ASTR>
__device__ __forceinline__ void gate_compute(
    const float* __restrict__ Wa, const float* __restrict__ Wb,
    const float* __restrict__ va, const float* __restrict__ vb,
    float* __restrict__ gbh, float* __restrict__ gbx,
    int gl, int kq, bool is_n, bool hiK, bool hiP)
{
#pragma unroll
    for (int rb = 0; rb < 4; ++rb) {
        u64 ax[8], ah[8];
#pragma unroll
        for (int r = 0; r < 8; ++r) { ax[r] = 0; ah[r] = 0; }
        // part A (ih): AQ quads
#pragma unroll
        for (int kk = 0; kk < AQ; ++kk) {
            ulonglong2 w = *(const ulonglong2*)(Wa + ((kk * GL_ + gl) * 4 + kq) * 4);
#pragma unroll
            for (int r = 0; r < 8; ++r) {
                ulonglong2 v = *(const ulonglong2*)
                    (va + (rb * 8 + r) * ASTR + kq * AOFF + kk * 4);
                ax[r] = fma2(w.x, v.x, ax[r]);
                ax[r] = fma2(w.y, v.y, ax[r]);
            }
        }
        // part B (hh): 8 quads, padded stride
#pragma unroll
        for (int kk = 0; kk < 8; ++kk) {
            ulonglong2 w = *(const ulonglong2*)(Wb + ((kk * GL_ + gl) * 4 + kq) * 4);
#pragma unroll
            for (int r = 0; r < 8; ++r) {
                ulonglong2 v = *(const ulonglong2*)
                    (vb + (rb * 8 + r) * HSTR + kq * 36 + kk * 4);
                ah[r] = fma2(w.x, v.x, ah[r]);
                ah[r] = fma2(w.y, v.y, ah[r]);
            }
        }
        if (!is_n) {  // warp-uniform branch (gates grouped by warp)
            float s[8];
#pragma unroll
            for (int r = 0; r < 8; ++r) s[r] = hsum2(ax[r]) + hsum2(ah[r]);
            float k4[4];
#pragma unroll
            for (int rr = 0; rr < 4; ++rr) {
                float snd = hiK ? s[rr] : s[4 + rr];
                float kp  = hiK ? s[4 + rr] : s[rr];
                k4[rr] = kp + __shfl_xor_sync(0xffffffffu, snd, 2, 4);
            }
#pragma unroll
            for (int rr = 0; rr < 2; ++rr) {
                float snd = hiP ? k4[rr] : k4[2 + rr];
                float kp  = hiP ? k4[2 + rr] : k4[rr];
                float f = kp + __shfl_xor_sync(0xffffffffu, snd, 1, 4);
                int row = rb * 8 + 2 * kq + rr;
                gbh[row * GL_ + gl] = f;
            }
        } else {      // n-gate: keep ih / hh parts separate
            float sx[8], sh[8];
#pragma unroll
            for (int r = 0; r < 8; ++r) { sx[r] = hsum2(ax[r]); sh[r] = hsum2(ah[r]); }
            float kx[4], kh[4];
#pragma unroll
            for (int rr = 0; rr < 4; ++rr) {
                float sndx = hiK ? sx[rr] : sx[4 + rr];
                float kpx  = hiK ? sx[4 + rr] : sx[rr];
                kx[rr] = kpx + __shfl_xor_sync(0xffffffffu, sndx, 2, 4);
                float sndh = hiK ? sh[rr] : sh[4 + rr];
                float kph  = hiK ? sh[4 + rr] : sh[rr];
                kh[rr] = kph + __shfl_xor_sync(0xffffffffu, sndh, 2, 4);
            }
#pragma unroll
            for (int rr = 0; rr < 2; ++rr) {
                float sndx = hiP ? kx[rr] : kx[2 + rr];
                float kpx  = hiP ? kx[2 + rr] : kx[rr];
                float fx = kpx + __shfl_xor_sync(0xffffffffu, sndx, 1, 4);
                float sndh = hiP ? kh[rr] : kh[2 + rr];
                float kph  = hiP ? kh[2 + rr] : kh[rr];
                float fh = kph + __shfl_xor_sync(0xffffffffu, sndh, 1, 4);
                int row = rb * 8 + 2 * kq + rr;
                gbh[row * GL_ + gl] = fh;
                gbx[row * UN_ + (gl - 64)] = fx;
            }
        }
    }
}

// ---------------- h update (threads 0..255) ----------------
__device__ __forceinline__ void h_update(
    float* __restrict__ hbuf, const float* __restrict__ gbh,
    const float* __restrict__ gbx, const float* __restrict__ bias,
    int tid, int crank)
{
    int j2 = (tid & 15) * 2;      // unit pair
    int rg = tid >> 4;            // 0..15 -> rows rg*2, rg*2+1
    float2 br  = *(const float2*)(bias + 0 * UN_ + j2);
    float2 bz  = *(const float2*)(bias + 1 * UN_ + j2);
    float2 bxn = *(const float2*)(bias + 2 * UN_ + j2);
    float2 bhn = *(const float2*)(bias + 3 * UN_ + j2);
#pragma unroll
    for (int rr = 0; rr < 2; ++rr) {
        int row = rg * 2 + rr;
        float2 gr = *(const float2*)(gbh + row * GL_ + j2);
        float2 gz = *(const float2*)(gbh + row * GL_ + UN_ + j2);
        float2 gn = *(const float2*)(gbh + row * GL_ + 2 * UN_ + j2);
        float2 gx = *(const float2*)(gbx + row * UN_ + j2);
        float* hp = hbuf + row * HSTR + crank * 36 + j2;
        float2 ho = *(const float2*)hp;
        float R0 = sigmoidf_(gr.x + br.x);
        float R1 = sigmoidf_(gr.y + br.y);
        float Z0 = sigmoidf_(gz.x + bz.x);
        float Z1 = sigmoidf_(gz.y + bz.y);
        float N0 = tanhf_(gx.x + bxn.x + R0 * (gn.x + bhn.x));
        float N1 = tanhf_(gx.y + bxn.y + R1 * (gn.y + bhn.y));
        float h0 = N0 + Z0 * (ho.x - N0);
        float h1 = N1 + Z1 * (ho.y - N1);
        uint32_t la = smem_u32(hp);
#pragma unroll
        for (int rk = 0; rk < CL_; ++rk)
            st_cluster_v2(la, rk, h0, h1);
    }
}

__global__ void __launch_bounds__(NTHR, 1) gru_cluster_kernel(
    const float* __restrict__ x,
    const int*   __restrict__ ticker,
    const float* __restrict__ embed,
    const float* __restrict__ b_ih0, const float* __restrict__ b_hh0,
    const float* __restrict__ b_ih1, const float* __restrict__ b_hh1,
    const float* __restrict__ head_w1, const float* __restrict__ head_b1,
    const float* __restrict__ head_w2, const float* __restrict__ head_b2,
    const float* __restrict__ W_ih0, const float* __restrict__ W_hh0,
    const float* __restrict__ W_ih1, const float* __restrict__ W_hh1,
    float* __restrict__ y)
{
    extern __shared__ __align__(16) float sm[];
    float* Wih0s = sm + OFF_WIH0;
    float* Whh0s = sm + OFF_WHH0;
    float* Wih1s = sm + OFF_WIH1;
    float* Whh1s = sm + OFF_WHH1;
    float* h0s   = sm + OFF_H0;
    float* h1s   = sm + OFF_H1;
    float* xs    = sm + OFF_XS;
    float* gbh   = sm + OFF_GBH;
    float* gbx   = sm + OFF_GBX;
    float* bias  = sm + OFF_BIAS;

    const int tid   = threadIdx.x;
    const int crank = blockIdx.x & 3;            // cluster rank (4,1,1)
    const int ci    = blockIdx.x >> 2;           // cluster id
    const int b0    = ci * RWS_;

    const int gl = tid >> 2;                     // gate 0..95
    const int kq = tid & 3;                      // k-quarter
    const bool is_n = (gl >= 64);
    const bool hiK = (kq & 2), hiP = (kq & 1);

    // ---- load weights into SMEM (one-time) ----
    // gate gl -> global row: type base + crank*32 + (gl & 31)
    for (int idx = tid; idx < GL_ * KX_; idx += NTHR) {
        int g = idx / KX_, k = idx % KX_;
        int grow = (g < 32 ? 0 : g < 64 ? H_ : 2 * H_) + crank * UN_ + (g & 31);
        int kqq = k / 12, kk = (k % 12) >> 2, i = k & 3;
        Wih0s[((kk * GL_ + g) * 4 + kqq) * 4 + i] = W_ih0[grow * KX_ + k];
    }
    for (int idx = tid; idx < GL_ * H_; idx += NTHR) {
        int g = idx / H_, k = idx % H_;
        int grow = (g < 32 ? 0 : g < 64 ? H_ : 2 * H_) + crank * UN_ + (g & 31);
        int kqq = k / 32, kk = (k % 32) >> 2, i = k & 3;
        int dst = ((kk * GL_ + g) * 4 + kqq) * 4 + i;
        Whh0s[dst] = W_hh0[grow * H_ + k];
        Wih1s[dst] = W_ih1[grow * H_ + k];
        Whh1s[dst] = W_hh1[grow * H_ + k];
    }
    if (tid < UN_) {
        int jr = crank * UN_ + tid;
        bias[0 * UN_ + tid] = b_ih0[jr] + b_hh0[jr];
        bias[1 * UN_ + tid] = b_ih0[H_ + jr] + b_hh0[H_ + jr];
        bias[2 * UN_ + tid] = b_ih0[2 * H_ + jr];
        bias[3 * UN_ + tid] = b_hh0[2 * H_ + jr];
        bias[4 * UN_ + tid] = b_ih1[jr] + b_hh1[jr];
        bias[5 * UN_ + tid] = b_ih1[H_ + jr] + b_hh1[H_ + jr];
        bias[6 * UN_ + tid] = b_ih1[2 * H_ + jr];
        bias[7 * UN_ + tid] = b_hh1[2 * H_ + jr];
    }
    for (int i = tid; i < RWS_ * HSTR; i += NTHR) { h0s[i] = 0.f; h1s[i] = 0.f; }
    // embedding (constant over t)
    for (int idx = tid; idx < RWS_ * E_; idx += NTHR) {
        int r = idx / E_, e = idx % E_;
        xs[r * KX_ + F_ + e] = embed[(size_t)ticker[b0 + r] * E_ + e];
    }
    // x(t=0)
    if (tid < 256) {
        int r = tid >> 3, c = tid & 7;
        *(float4*)(xs + r * KX_ + c * 4) =
            *(const float4*)(x + ((size_t)(b0 + r) * T_) * F_ + c * 4);
    }
    __syncthreads();

    // ---- recurrent loop ----
    for (int t = 0; t < T_; ++t) {
        // A: layer-0 gates (reads xs, h0s)
        gate_compute<3, 12, KX_>(Wih0s, Whh0s, xs, h0s, gbh, gbx,
                                 gl, kq, is_n, hiK, hiP);
        CLUSTER_SYNC();                            // s1: all done reading h0_old
        // C: update h0 (writes all 4 CTAs) ; spare warps stage x(t+1)
        if (tid < 256) {
            h_update(h0s, gbh, gbx, bias, tid, crank);
        } else if (t + 1 < T_) {
            int u = tid - 256;                     // 0..127
            int r = u >> 2, c = u & 3;             // 32 rows x 4 float4
            *(float4*)(xs + r * KX_ + c * 8) =
                *(const float4*)(x + ((size_t)(b0 + r) * T_ + (t + 1)) * F_ + c * 8);
            *(float4*)(xs + r * KX_ + c * 8 + 4) =
                *(const float4*)(x + ((size_t)(b0 + r) * T_ + (t + 1)) * F_ + c * 8 + 4);
        }
        CLUSTER_SYNC();                            // s2: h0_new visible everywhere
        // E: layer-1 gates (reads h0s, h1s)
        gate_compute<8, 36, HSTR>(Wih1s, Whh1s, h0s, h1s, gbh, gbx,
                                  gl, kq, is_n, hiK, hiP);
        CLUSTER_SYNC();                            // s3: all done reading h1_old
        // G: update h1
        if (tid < 256)
            h_update(h1s, gbh, gbx, bias + 4 * UN_, tid, crank);
        __syncthreads();                           // protect gbh vs next layer-0
    }
    CLUSTER_SYNC();                                // final h1 visible for head

    // ---- head: this CTA handles local rows [crank*8, crank*8+8) ----
    float* scratch = gbh;                          // 8*128 floats fits
    if (tid < H_) {
        const int u = tid;
        const float w2  = head_w2[u];
        const float b1v = head_b1[u];
        float acc[8];
#pragma unroll
        for (int r = 0; r < 8; ++r) acc[r] = b1v;
#pragma unroll
        for (int c = 0; c < 4; ++c)
            for (int kk = 0; kk < 8; ++kk) {
                float4 w = *(const float4*)(head_w1 + (size_t)u * H_ + c * 32 + kk * 4);
#pragma unroll
                for (int r = 0; r < 8; ++r) {
                    int lrow = crank * 8 + r;
                    float4 v = *(const float4*)(h1s + lrow * HSTR + c * 36 + kk * 4);
                    acc[r] += w.x * v.x + w.y * v.y + w.z * v.z + w.w * v.w;
                }
            }
#pragma unroll
        for (int r = 0; r < 8; ++r)
            scratch[r * H_ + u] = fmaxf(acc[r], 0.f) * w2;
    }
    __syncthreads();
    if (tid < 8) {
        float acc = head_b2[0];
        for (int k = 0; k < H_; ++k) acc += scratch[tid * H_ + k];
        y[b0 + crank * 8 + tid] = acc;
    }
}

extern "C" void kernel_launch(void* const* d_in, const int* in_sizes, int n_in,
                              void* d_out, int out_size) {
    const float* x       = (const float*)d_in[0];
    const int*   ticker  = (const int*)  d_in[1];
    const float* embed   = (const float*)d_in[2];
    const float* W_ih0   = (const float*)d_in[3];
    const float* W_hh0   = (const float*)d_in[4];
    const float* b_ih0   = (const float*)d_in[5];
    const float* b_hh0   = (const float*)d_in[6];
    const float* W_ih1   = (const float*)d_in[7];
    const float* W_hh1   = (const float*)d_in[8];
    const float* b_ih1   = (const float*)d_in[9];
    const float* b_hh1   = (const float*)d_in[10];
    const float* head_w1 = (const float*)d_in[11];
    const float* head_b1 = (const float*)d_in[12];
    const float* head_w2 = (const float*)d_in[13];
    const float* head_b2 = (const float*)d_in[14];

    cudaFuncSetAttribute(gru_cluster_kernel,
                         cudaFuncAttributeMaxDynamicSharedMemorySize, SMEM_BYTES);

    cudaLaunchConfig_t cfg = {};
    cfg.gridDim  = dim3(NCTA, 1, 1);
    cfg.blockDim = dim3(NTHR, 1, 1);
    cfg.dynamicSmemBytes = SMEM_BYTES;
    cfg.stream = 0;
    cudaLaunchAttribute attr[1];
    attr[0].id = cudaLaunchAttributeClusterDimension;
    attr[0].val.clusterDim.x = CL_;
    attr[0].val.clusterDim.y = 1;
    attr[0].val.clusterDim.z = 1;
    cfg.attrs = attr;
    cfg.numAttrs = 1;

    cudaLaunchKernelEx(&cfg, gru_cluster_kernel,
                       x, ticker, embed,
                       b_ih0, b_hh0, b_ih1, b_hh1,
                       head_w1, head_b1, head_w2, head_b2,
                       W_ih0, W_hh0, W_ih1, W_hh1,
                       (float*)d_out);
}

// round 6
// speedup vs baseline: 1.6967x; 1.0002x over previous
#include <cuda_runtime.h>
#include <cstdint>

#define B_    1024
#define T_    512
#define F_    32
#define E_    16
#define H_    128
#define KX_   48          // F + E
#define CL_   4           // CTAs per cluster
#define UN_   32          // hidden units per CTA
#define GL_   96          // gate outputs per CTA (3 * UN_)
#define RWS_  32          // batch rows per cluster
#define NCTA  128         // 32 clusters * 4
#define NTHR  384         // tid = gl*4 + kq
#define HSTR  144         // padded h row stride (floats): 4 chunks of 36

typedef unsigned long long u64;

// ---------------- SMEM layout (floats) ----------------
#define OFF_WIH0   0                         // 96*48      = 4608
#define OFF_WHH0   (OFF_WIH0 + GL_*KX_)      // 96*128     = 12288
#define OFF_WIH1   (OFF_WHH0 + GL_*H_)
#define OFF_WHH1   (OFF_WIH1 + GL_*H_)
#define OFF_H0     (OFF_WHH1 + GL_*H_)       // 32*144     = 4608
#define OFF_H1     (OFF_H0 + RWS_*HSTR)
#define OFF_XS     (OFF_H1 + RWS_*HSTR)      // 32*48      = 1536
#define OFF_GBH    (OFF_XS + RWS_*KX_)       // 32*96      = 3072
#define OFF_GBX    (OFF_GBH + RWS_*GL_)      // 32*32      = 1024
#define OFF_BIAS   (OFF_GBX + RWS_*UN_)      // 8*32       = 256
#define SMEM_FLOATS (OFF_BIAS + 256)
#define SMEM_BYTES  (SMEM_FLOATS * 4)        // 226,304 B

// ---------------- helpers ----------------
__device__ __forceinline__ u64 fma2(u64 a, u64 b, u64 c) {
    u64 d;
    asm("fma.rn.f32x2 %0, %1, %2, %3;" : "=l"(d) : "l"(a), "l"(b), "l"(c));
    return d;
}
__device__ __forceinline__ float hsum2(u64 a) {
    float l, h;
    asm("mov.b64 {%0, %1}, %2;" : "=f"(l), "=f"(h) : "l"(a));
    return l + h;
}
__device__ __forceinline__ float sigmoidf_(float v) {
    return 1.f / (1.f + __expf(-v));
}
__device__ __forceinline__ float tanhf_(float v) {
    v = fminf(fmaxf(v, -15.f), 15.f);
    float e = __expf(2.f * v);
    return (e - 1.f) / (e + 1.f);
}
__device__ __forceinline__ uint32_t smem_u32(const void* p) {
    uint32_t a;
    asm("{ .reg .u64 t; cvta.to.shared.u64 t, %1; cvt.u32.u64 %0, t; }"
        : "=r"(a) : "l"(p));
    return a;
}
__device__ __forceinline__ void st_cluster_v2(uint32_t laddr, int rank,
                                              float a, float b) {
    asm volatile(
        "{ .reg .b32 ra;\n\t"
        "mapa.shared::cluster.u32 ra, %0, %1;\n\t"
        "st.shared::cluster.v2.f32 [ra], {%2, %3}; }"
        :: "r"(laddr), "r"(rank), "f"(a), "f"(b) : "memory");
}
#define CLUSTER_SYNC() do { \
    asm volatile("barrier.cluster.arrive.aligned;" ::: "memory"); \
    asm volatile("barrier.cluster.wait.aligned;"   ::: "memory"); \
} while (0)

// ---------------- per-layer gate compute ----------------
// Thread (gl, kq) accumulates its K-quarter of gate gl over 32 rows
// (4 blocks of 8), shfl-reduces across kq, writes finalized pre-activations
// for rows {rb*8+2kq, rb*8+2kq+1} into gb buffers.
template<int AQ, int AOFF, int ASTR>
__device__ __forceinline__ void gate_compute(
    const float* __restrict__ Wa, const float* __restrict__ Wb,
    const float* __restrict__ va, const float* __restrict__ vb,
    float* __restrict__ gbh, float* __restrict__ gbx,
    int gl, int kq, bool is_n, bool hiK, bool hiP)
{
#pragma unroll
    for (int rb = 0; rb < 4; ++rb) {
        u64 ax[8], ah[8];
#pragma unroll
        for (int r = 0; r < 8; ++r) { ax[r] = 0; ah[r] = 0; }
        // part A (ih): AQ quads
#pragma unroll
        for (int kk = 0; kk < AQ; ++kk) {
            ulonglong2 w = *(const ulonglong2*)(Wa + ((kk * GL_ + gl) * 4 + kq) * 4);
#pragma unroll
            for (int r = 0; r < 8; ++r) {
                ulonglong2 v = *(const ulonglong2*)
                    (va + (rb * 8 + r) * ASTR + kq * AOFF + kk * 4);
                ax[r] = fma2(w.x, v.x, ax[r]);
                ax[r] = fma2(w.y, v.y, ax[r]);
            }
        }
        // part B (hh): 8 quads, padded stride
#pragma unroll
        for (int kk = 0; kk < 8; ++kk) {
            ulonglong2 w = *(const ulonglong2*)(Wb + ((kk * GL_ + gl) * 4 + kq) * 4);
#pragma unroll
            for (int r = 0; r < 8; ++r) {
                ulonglong2 v = *(const ulonglong2*)
                    (vb + (rb * 8 + r) * HSTR + kq * 36 + kk * 4);
                ah[r] = fma2(w.x, v.x, ah[r]);
                ah[r] = fma2(w.y, v.y, ah[r]);
            }
        }
        if (!is_n) {  // warp-uniform branch (gates grouped by warp)
            float s[8];
#pragma unroll
            for (int r = 0; r < 8; ++r) s[r] = hsum2(ax[r]) + hsum2(ah[r]);
            float k4[4];
#pragma unroll
            for (int rr = 0; rr < 4; ++rr) {
                float snd = hiK ? s[rr] : s[4 + rr];
                float kp  = hiK ? s[4 + rr] : s[rr];
                k4[rr] = kp + __shfl_xor_sync(0xffffffffu, snd, 2, 4);
            }
#pragma unroll
            for (int rr = 0; rr < 2; ++rr) {
                float snd = hiP ? k4[rr] : k4[2 + rr];
                float kp  = hiP ? k4[2 + rr] : k4[rr];
                float f = kp + __shfl_xor_sync(0xffffffffu, snd, 1, 4);
                int row = rb * 8 + 2 * kq + rr;
                gbh[row * GL_ + gl] = f;
            }
        } else {      // n-gate: keep ih / hh parts separate
            float sx[8], sh[8];
#pragma unroll
            for (int r = 0; r < 8; ++r) { sx[r] = hsum2(ax[r]); sh[r] = hsum2(ah[r]); }
            float kx[4], kh[4];
#pragma unroll
            for (int rr = 0; rr < 4; ++rr) {
                float sndx = hiK ? sx[rr] : sx[4 + rr];
                float kpx  = hiK ? sx[4 + rr] : sx[rr];
                kx[rr] = kpx + __shfl_xor_sync(0xffffffffu, sndx, 2, 4);
                float sndh = hiK ? sh[rr] : sh[4 + rr];
                float kph  = hiK ? sh[4 + rr] : sh[rr];
                kh[rr] = kph + __shfl_xor_sync(0xffffffffu, sndh, 2, 4);
            }
#pragma unroll
            for (int rr = 0; rr < 2; ++rr) {
                float sndx = hiP ? kx[rr] : kx[2 + rr];
                float kpx  = hiP ? kx[2 + rr] : kx[rr];
                float fx = kpx + __shfl_xor_sync(0xffffffffu, sndx, 1, 4);
                float sndh = hiP ? kh[rr] : kh[2 + rr];
                float kph  = hiP ? kh[2 + rr] : kh[rr];
                float fh = kph + __shfl_xor_sync(0xffffffffu, sndh, 1, 4);
                int row = rb * 8 + 2 * kq + rr;
                gbh[row * GL_ + gl] = fh;
                gbx[row * UN_ + (gl - 64)] = fx;
            }
        }
    }
}

// ---------------- h update (threads 0..255) ----------------
__device__ __forceinline__ void h_update(
    float* __restrict__ hbuf, const float* __restrict__ gbh,
    const float* __restrict__ gbx, const float* __restrict__ bias,
    int tid, int crank)
{
    int j2 = (tid & 15) * 2;      // unit pair
    int rg = tid >> 4;            // 0..15 -> rows rg*2, rg*2+1
    float2 br  = *(const float2*)(bias + 0 * UN_ + j2);
    float2 bz  = *(const float2*)(bias + 1 * UN_ + j2);
    float2 bxn = *(const float2*)(bias + 2 * UN_ + j2);
    float2 bhn = *(const float2*)(bias + 3 * UN_ + j2);
#pragma unroll
    for (int rr = 0; rr < 2; ++rr) {
        int row = rg * 2 + rr;
        float2 gr = *(const float2*)(gbh + row * GL_ + j2);
        float2 gz = *(const float2*)(gbh + row * GL_ + UN_ + j2);
        float2 gn = *(const float2*)(gbh + row * GL_ + 2 * UN_ + j2);
        float2 gx = *(const float2*)(gbx + row * UN_ + j2);
        float* hp = hbuf + row * HSTR + crank * 36 + j2;
        float2 ho = *(const float2*)hp;
        float R0 = sigmoidf_(gr.x + br.x);
        float R1 = sigmoidf_(gr.y + br.y);
        float Z0 = sigmoidf_(gz.x + bz.x);
        float Z1 = sigmoidf_(gz.y + bz.y);
        float N0 = tanhf_(gx.x + bxn.x + R0 * (gn.x + bhn.x));
        float N1 = tanhf_(gx.y + bxn.y + R1 * (gn.y + bhn.y));
        float h0 = N0 + Z0 * (ho.x - N0);
        float h1 = N1 + Z1 * (ho.y - N1);
        uint32_t la = smem_u32(hp);
#pragma unroll
        for (int rk = 0; rk < CL_; ++rk)
            st_cluster_v2(la, rk, h0, h1);
    }
}

__global__ void __launch_bounds__(NTHR, 1) gru_cluster_kernel(
    const float* __restrict__ x,
    const int*   __restrict__ ticker,
    const float* __restrict__ embed,
    const float* __restrict__ b_ih0, const float* __restrict__ b_hh0,
    const float* __restrict__ b_ih1, const float* __restrict__ b_hh1,
    const float* __restrict__ head_w1, const float* __restrict__ head_b1,
    const float* __restrict__ head_w2, const float* __restrict__ head_b2,
    const float* __restrict__ W_ih0, const float* __restrict__ W_hh0,
    const float* __restrict__ W_ih1, const float* __restrict__ W_hh1,
    float* __restrict__ y)
{
    extern __shared__ __align__(16) float sm[];
    float* Wih0s = sm + OFF_WIH0;
    float* Whh0s = sm + OFF_WHH0;
    float* Wih1s = sm + OFF_WIH1;
    float* Whh1s = sm + OFF_WHH1;
    float* h0s   = sm + OFF_H0;
    float* h1s   = sm + OFF_H1;
    float* xs    = sm + OFF_XS;
    float* gbh   = sm + OFF_GBH;
    float* gbx   = sm + OFF_GBX;
    float* bias  = sm + OFF_BIAS;

    const int tid   = threadIdx.x;
    const int crank = blockIdx.x & 3;            // cluster rank (4,1,1)
    const int ci    = blockIdx.x >> 2;           // cluster id
    const int b0    = ci * RWS_;

    const int gl = tid >> 2;                     // gate 0..95
    const int kq = tid & 3;                      // k-quarter
    const bool is_n = (gl >= 64);
    const bool hiK = (kq & 2), hiP = (kq & 1);

    // ---- load weights into SMEM (one-time) ----
    // gate gl -> global row: type base + crank*32 + (gl & 31)
    for (int idx = tid; idx < GL_ * KX_; idx += NTHR) {
        int g = idx / KX_, k = idx % KX_;
        int grow = (g < 32 ? 0 : g < 64 ? H_ : 2 * H_) + crank * UN_ + (g & 31);
        int kqq = k / 12, kk = (k % 12) >> 2, i = k & 3;
        Wih0s[((kk * GL_ + g) * 4 + kqq) * 4 + i] = W_ih0[grow * KX_ + k];
    }
    for (int idx = tid; idx < GL_ * H_; idx += NTHR) {
        int g = idx / H_, k = idx % H_;
        int grow = (g < 32 ? 0 : g < 64 ? H_ : 2 * H_) + crank * UN_ + (g & 31);
        int kqq = k / 32, kk = (k % 32) >> 2, i = k & 3;
        int dst = ((kk * GL_ + g) * 4 + kqq) * 4 + i;
        Whh0s[dst] = W_hh0[grow * H_ + k];
        Wih1s[dst] = W_ih1[grow * H_ + k];
        Whh1s[dst] = W_hh1[grow * H_ + k];
    }
    if (tid < UN_) {
        int jr = crank * UN_ + tid;
        bias[0 * UN_ + tid] = b_ih0[jr] + b_hh0[jr];
        bias[1 * UN_ + tid] = b_ih0[H_ + jr] + b_hh0[H_ + jr];
        bias[2 * UN_ + tid] = b_ih0[2 * H_ + jr];
        bias[3 * UN_ + tid] = b_hh0[2 * H_ + jr];
        bias[4 * UN_ + tid] = b_ih1[jr] + b_hh1[jr];
        bias[5 * UN_ + tid] = b_ih1[H_ + jr] + b_hh1[H_ + jr];
        bias[6 * UN_ + tid] = b_ih1[2 * H_ + jr];
        bias[7 * UN_ + tid] = b_hh1[2 * H_ + jr];
    }
    for (int i = tid; i < RWS_ * HSTR; i += NTHR) { h0s[i] = 0.f; h1s[i] = 0.f; }
    // embedding (constant over t)
    for (int idx = tid; idx < RWS_ * E_; idx += NTHR) {
        int r = idx / E_, e = idx % E_;
        xs[r * KX_ + F_ + e] = embed[(size_t)ticker[b0 + r] * E_ + e];
    }
    // x(t=0)
    if (tid < 256) {
        int r = tid >> 3, c = tid & 7;
        *(float4*)(xs + r * KX_ + c * 4) =
            *(const float4*)(x + ((size_t)(b0 + r) * T_) * F_ + c * 4);
    }
    __syncthreads();

    // ---- recurrent loop ----
    for (int t = 0; t < T_; ++t) {
        // A: layer-0 gates (reads xs, h0s)
        gate_compute<3, 12, KX_>(Wih0s, Whh0s, xs, h0s, gbh, gbx,
                                 gl, kq, is_n, hiK, hiP);
        CLUSTER_SYNC();                            // s1: all done reading h0_old
        // C: update h0 (writes all 4 CTAs) ; spare warps stage x(t+1)
        if (tid < 256) {
            h_update(h0s, gbh, gbx, bias, tid, crank);
        } else if (t + 1 < T_) {
            int u = tid - 256;                     // 0..127
            int r = u >> 2, c = u & 3;             // 32 rows x 4 float4
            *(float4*)(xs + r * KX_ + c * 8) =
                *(const float4*)(x + ((size_t)(b0 + r) * T_ + (t + 1)) * F_ + c * 8);
            *(float4*)(xs + r * KX_ + c * 8 + 4) =
                *(const float4*)(x + ((size_t)(b0 + r) * T_ + (t + 1)) * F_ + c * 8 + 4);
        }
        CLUSTER_SYNC();                            // s2: h0_new visible everywhere
        // E: layer-1 gates (reads h0s, h1s)
        gate_compute<8, 36, HSTR>(Wih1s, Whh1s, h0s, h1s, gbh, gbx,
                                  gl, kq, is_n, hiK, hiP);
        CLUSTER_SYNC();                            // s3: all done reading h1_old
        // G: update h1
        if (tid < 256)
            h_update(h1s, gbh, gbx, bias + 4 * UN_, tid, crank);
        __syncthreads();                           // protect gbh vs next layer-0
    }
    CLUSTER_SYNC();                                // final h1 visible for head

    // ---- head: this CTA handles local rows [crank*8, crank*8+8) ----
    float* scratch = gbh;                          // 8*128 floats fits
    if (tid < H_) {
        const int u = tid;
        const float w2  = head_w2[u];
        const float b1v = head_b1[u];
        float acc[8];
#pragma unroll
        for (int r = 0; r < 8; ++r) acc[r] = b1v;
#pragma unroll
        for (int c = 0; c < 4; ++c)
            for (int kk = 0; kk < 8; ++kk) {
                float4 w = *(const float4*)(head_w1 + (size_t)u * H_ + c * 32 + kk * 4);
#pragma unroll
                for (int r = 0; r < 8; ++r) {
                    int lrow = crank * 8 + r;
                    float4 v = *(const float4*)(h1s + lrow * HSTR + c * 36 + kk * 4);
                    acc[r] += w.x * v.x + w.y * v.y + w.z * v.z + w.w * v.w;
                }
            }
#pragma unroll
        for (int r = 0; r < 8; ++r)
            scratch[r * H_ + u] = fmaxf(acc[r], 0.f) * w2;
    }
    __syncthreads();
    if (tid < 8) {
        float acc = head_b2[0];
        for (int k = 0; k < H_; ++k) acc += scratch[tid * H_ + k];
        y[b0 + crank * 8 + tid] = acc;
    }
}

extern "C" void kernel_launch(void* const* d_in, const int* in_sizes, int n_in,
                              void* d_out, int out_size) {
    const float* x       = (const float*)d_in[0];
    const int*   ticker  = (const int*)  d_in[1];
    const float* embed   = (const float*)d_in[2];
    const float* W_ih0   = (const float*)d_in[3];
    const float* W_hh0   = (const float*)d_in[4];
    const float* b_ih0   = (const float*)d_in[5];
    const float* b_hh0   = (const float*)d_in[6];
    const float* W_ih1   = (const float*)d_in[7];
    const float* W_hh1   = (const float*)d_in[8];
    const float* b_ih1   = (const float*)d_in[9];
    const float* b_hh1   = (const float*)d_in[10];
    const float* head_w1 = (const float*)d_in[11];
    const float* head_b1 = (const float*)d_in[12];
    const float* head_w2 = (const float*)d_in[13];
    const float* head_b2 = (const float*)d_in[14];

    cudaFuncSetAttribute(gru_cluster_kernel,
                         cudaFuncAttributeMaxDynamicSharedMemorySize, SMEM_BYTES);

    cudaLaunchConfig_t cfg = {};
    cfg.gridDim  = dim3(NCTA, 1, 1);
    cfg.blockDim = dim3(NTHR, 1, 1);
    cfg.dynamicSmemBytes = SMEM_BYTES;
    cfg.stream = 0;
    cudaLaunchAttribute attr[1];
    attr[0].id = cudaLaunchAttributeClusterDimension;
    attr[0].val.clusterDim.x = CL_;
    attr[0].val.clusterDim.y = 1;
    attr[0].val.clusterDim.z = 1;
    cfg.attrs = attr;
    cfg.numAttrs = 1;

    cudaLaunchKernelEx(&cfg, gru_cluster_kernel,
                       x, ticker, embed,
                       b_ih0, b_hh0, b_ih1, b_hh1,
                       head_w1, head_b1, head_w2, head_b2,
                       W_ih0, W_hh0, W_ih1, W_hh1,
                       (float*)d_out);
}

// round 7
// speedup vs baseline: 2.8627x; 1.6872x over previous
#include <cuda_runtime.h>
#include <cstdint>

#define T_    512
#define F_    32
#define E_    16
#define H_    128
#define KX_   48
#define CL_   4
#define UN_   32
#define RWS_  32
#define NCTA  128
#define NTHR  256

typedef unsigned long long u64;

// SMEM (floats). Weights: [kk][gate_type][u][kq][4] -> kk*1536 + gt*512 + u*16 + kq*4
#define OFF_WIH0 0
#define OFF_WHH0 (OFF_WIH0 + 3*1536)          // 4608
#define OFF_WIH1 (OFF_WHH0 + 8*1536)          // 16896
#define OFF_WHH1 (OFF_WIH1 + 8*1536)          // 29184
#define OFF_H0   (OFF_WHH1 + 8*1536)          // 41472 ; 2 buffers
#define OFF_H1   (OFF_H0 + 2*RWS_*H_)         // 49664 ; single buffer
#define OFF_X    (OFF_H1 + RWS_*H_)           // 53760 ; single buffer
#define SMEM_FLOATS (OFF_X + RWS_*KX_)        // 55296
#define SMEM_BYTES  (SMEM_FLOATS * 4)         // 221184

__device__ __forceinline__ u64 fma2(u64 a, u64 b, u64 c) {
    u64 d;
    asm("fma.rn.f32x2 %0, %1, %2, %3;" : "=l"(d) : "l"(a), "l"(b), "l"(c));
    return d;
}
__device__ __forceinline__ float hsum2(u64 a) {
    float l, h;
    asm("mov.b64 {%0, %1}, %2;" : "=f"(l), "=f"(h) : "l"(a));
    return l + h;
}
__device__ __forceinline__ float sigmoidf_(float v) {
    return 1.f / (1.f + __expf(-v));
}
__device__ __forceinline__ float tanhf_(float v) {
    v = fminf(fmaxf(v, -15.f), 15.f);
    float e = __expf(2.f * v);
    return (e - 1.f) / (e + 1.f);
}
__device__ __forceinline__ uint32_t smem_u32(const void* p) {
    uint32_t a;
    asm("{ .reg .u64 t; cvta.to.shared.u64 t, %1; cvt.u32.u64 %0, t; }"
        : "=r"(a) : "l"(p));
    return a;
}
__device__ __forceinline__ void st_cluster_f32(uint32_t laddr, int rank, float v) {
    asm volatile(
        "{ .reg .b32 ra;\n\t"
        "mapa.shared::cluster.u32 ra, %0, %1;\n\t"
        "st.shared::cluster.f32 [ra], %2; }"
        :: "r"(laddr), "r"(rank), "f"(v) : "memory");
}
#define CLUSTER_SYNC() do { \
    asm volatile("barrier.cluster.arrive.aligned;" ::: "memory"); \
    asm volatile("barrier.cluster.wait.aligned;"   ::: "memory"); \
} while (0)

// Accumulate one 8-row block: ih part (NIH quads, stride SIH) feeds r,z,xn;
// hh part (8 quads, stride H_) feeds r,z,hn.
template<int NIH, int SIH>
__device__ __forceinline__ void block_accum(
    const float* __restrict__ Wih, const float* __restrict__ Whh,
    const float* __restrict__ vih, const float* __restrict__ vhh,
    int tb, int kqo,
    u64* __restrict__ Ar, u64* __restrict__ Az,
    u64* __restrict__ Ax, u64* __restrict__ Ah)
{
#pragma unroll
    for (int r = 0; r < 8; ++r) { Ar[r] = 0; Az[r] = 0; Ax[r] = 0; Ah[r] = 0; }
#pragma unroll
    for (int kk = 0; kk < NIH; ++kk) {
        const float* wp = Wih + kk * 1536 + tb;
        ulonglong2 wr = *(const ulonglong2*)wp;
        ulonglong2 wz = *(const ulonglong2*)(wp + 512);
        ulonglong2 wn = *(const ulonglong2*)(wp + 1024);
#pragma unroll
        for (int r = 0; r < 8; ++r) {
            ulonglong2 v = *(const ulonglong2*)(vih + r * SIH + kk * 16 + kqo);
            Ar[r] = fma2(wr.x, v.x, Ar[r]); Ar[r] = fma2(wr.y, v.y, Ar[r]);
            Az[r] = fma2(wz.x, v.x, Az[r]); Az[r] = fma2(wz.y, v.y, Az[r]);
            Ax[r] = fma2(wn.x, v.x, Ax[r]); Ax[r] = fma2(wn.y, v.y, Ax[r]);
        }
    }
#pragma unroll
    for (int kk = 0; kk < 8; ++kk) {
        const float* wp = Whh + kk * 1536 + tb;
        ulonglong2 wr = *(const ulonglong2*)wp;
        ulonglong2 wz = *(const ulonglong2*)(wp + 512);
        ulonglong2 wn = *(const ulonglong2*)(wp + 1024);
#pragma unroll
        for (int r = 0; r < 8; ++r) {
            ulonglong2 v = *(const ulonglong2*)(vhh + r * H_ + kk * 16 + kqo);
            Ar[r] = fma2(wr.x, v.x, Ar[r]); Ar[r] = fma2(wr.y, v.y, Ar[r]);
            Az[r] = fma2(wz.x, v.x, Az[r]); Az[r] = fma2(wz.y, v.y, Az[r]);
            Ah[r] = fma2(wn.x, v.x, Ah[r]); Ah[r] = fma2(wn.y, v.y, Ah[r]);
        }
    }
}

#define RED4(kout, s) \
    _Pragma("unroll") \
    for (int rr = 0; rr < 4; ++rr) { \
        float snd = hiK ? (s)[rr] : (s)[4 + rr]; \
        float kp  = hiK ? (s)[4 + rr] : (s)[rr]; \
        (kout)[rr] = kp + __shfl_xor_sync(0xffffffffu, snd, 2, 4); }
#define RED2(f, kin, rr) { \
        float snd = hiP ? (kin)[rr] : (kin)[2 + rr]; \
        float kp  = hiP ? (kin)[2 + rr] : (kin)[rr]; \
        f = kp + __shfl_xor_sync(0xffffffffu, snd, 1, 4); }

// Cross-kq reduce of 4 quantities over 8 rows; lane kq finalizes rows 2kq,2kq+1.
__device__ __forceinline__ void finalize2(
    const u64* Ar, const u64* Az, const u64* Ax, const u64* Ah,
    float br, float bz, float bxn, float bhn,
    bool hiK, bool hiP, float* hown, float* hout)
{
    float sr[8], sz[8], sx[8], sh[8];
#pragma unroll
    for (int r = 0; r < 8; ++r) {
        sr[r] = hsum2(Ar[r]); sz[r] = hsum2(Az[r]);
        sx[r] = hsum2(Ax[r]); sh[r] = hsum2(Ah[r]);
    }
    float kr[4], kz[4], kx[4], kh[4];
    RED4(kr, sr); RED4(kz, sz); RED4(kx, sx); RED4(kh, sh);
#pragma unroll
    for (int rr = 0; rr < 2; ++rr) {
        float fr, fz, fx, fh;
        RED2(fr, kr, rr); RED2(fz, kz, rr); RED2(fx, kx, rr); RED2(fh, kh, rr);
        float R = sigmoidf_(fr + br);
        float Z = sigmoidf_(fz + bz);
        float N = tanhf_(fx + bxn + R * (fh + bhn));
        float h = N + Z * (hown[rr] - N);
        hown[rr] = h;
        hout[rr] = h;
    }
}

__global__ void __launch_bounds__(NTHR, 1) gru_kernel(
    const float* __restrict__ x,
    const int*   __restrict__ ticker,
    const float* __restrict__ embed,
    const float* __restrict__ b_ih0, const float* __restrict__ b_hh0,
    const float* __restrict__ b_ih1, const float* __restrict__ b_hh1,
    const float* __restrict__ head_w1, const float* __restrict__ head_b1,
    const float* __restrict__ head_w2, const float* __restrict__ head_b2,
    const float* __restrict__ W_ih0, const float* __restrict__ W_hh0,
    const float* __restrict__ W_ih1, const float* __restrict__ W_hh1,
    float* __restrict__ y)
{
    extern __shared__ __align__(16) float sm[];
    const int tid   = threadIdx.x;
    const int kq    = tid & 3;
    const int u     = (tid >> 2) & 31;       // local unit
    const int rh    = tid >> 7;              // row half
    const int crank = blockIdx.x & 3;
    const int b0    = (blockIdx.x >> 2) * RWS_;

    const int  tb   = u * 16 + kq * 4;       // weight thread base
    const int  kqo  = kq * 4;                // operand kq offset
    const bool hiK  = kq & 2, hiP = kq & 1;
    const int  posu = (u >> 2) * 16 + crank * 4 + (u & 3);  // h position of my unit
    const int  rowb = rh * 16;

    // ---- one-time weight remap into SMEM ----
    for (int idx = tid; idx < 96 * KX_; idx += NTHR) {
        int g = idx / KX_, k = idx % KX_;
        int gt = g / 32, uu = g & 31;
        int kqq = k / 12, kk = (k % 12) >> 2, i = k & 3;
        sm[OFF_WIH0 + kk * 1536 + gt * 512 + uu * 16 + kqq * 4 + i] =
            W_ih0[(size_t)(gt * H_ + crank * UN_ + uu) * KX_ + k];
    }
    for (int idx = tid; idx < 96 * H_; idx += NTHR) {
        int g = idx / H_, k = idx % H_;
        int gt = g / 32, uu = g & 31;
        int kqq = k >> 5, kk = (k & 31) >> 2, i = k & 3;
        int dst = kk * 1536 + gt * 512 + uu * 16 + kqq * 4 + i;
        size_t grow = (size_t)(gt * H_ + crank * UN_ + uu);
        sm[OFF_WHH0 + dst] = W_hh0[grow * H_ + k];
        sm[OFF_WIH1 + dst] = W_ih1[grow * H_ + k];
        sm[OFF_WHH1 + dst] = W_hh1[grow * H_ + k];
    }
    for (int i = tid; i < 2 * RWS_ * H_; i += NTHR) sm[OFF_H0 + i] = 0.f;
    for (int i = tid; i < RWS_ * H_; i += NTHR)     sm[OFF_H1 + i] = 0.f;
    // embedding (constant, pos-mapped, never overwritten by x staging)
    for (int idx = tid; idx < RWS_ * E_; idx += NTHR) {
        int r = idx >> 4, e = idx & 15, k = F_ + e;
        int kqq = k / 12, kk = (k % 12) >> 2, i = k & 3;
        sm[OFF_X + r * KX_ + kk * 16 + kqq * 4 + i] =
            embed[(size_t)ticker[b0 + r] * E_ + e];
    }
    // x(t=0), pos-mapped
    {
        int r = tid >> 3, q = tid & 7;
        int kqq = q / 3, kk = q - 3 * kqq;
        *(float4*)&sm[OFF_X + r * KX_ + kk * 16 + kqq * 4] =
            *(const float4*)(x + ((size_t)(b0 + r) * T_) * F_ + q * 4);
    }
    // biases for my unit
    const int jr = crank * UN_ + u;
    const float br0  = b_ih0[jr] + b_hh0[jr];
    const float bz0  = b_ih0[H_ + jr] + b_hh0[H_ + jr];
    const float bxn0 = b_ih0[2 * H_ + jr], bhn0 = b_hh0[2 * H_ + jr];
    const float br1  = b_ih1[jr] + b_hh1[jr];
    const float bz1  = b_ih1[H_ + jr] + b_hh1[H_ + jr];
    const float bxn1 = b_ih1[2 * H_ + jr], bhn1 = b_hh1[2 * H_ + jr];

    float h0own[4] = {0.f, 0.f, 0.f, 0.f};
    float h1own[4] = {0.f, 0.f, 0.f, 0.f};

    __syncthreads();
    CLUSTER_SYNC();

    float* xs  = sm + OFF_X;
    float* h1s = sm + OFF_H1;

    for (int t = 0; t < T_; ++t) {
        const float* h0cur = sm + OFF_H0 + (t & 1) * RWS_ * H_;
        float*       h0nxt = sm + OFF_H0 + ((t + 1) & 1) * RWS_ * H_;
        u64 Ar[8], Az[8], Ax[8], Ah[8];
        float hA[4];

        // ---------- layer 0 ----------
#pragma unroll
        for (int rb = 0; rb < 2; ++rb) {
            block_accum<3, KX_>(sm + OFF_WIH0, sm + OFF_WHH0,
                                xs + (rowb + rb * 8) * KX_,
                                h0cur + (rowb + rb * 8) * H_,
                                tb, kqo, Ar, Az, Ax, Ah);
            finalize2(Ar, Az, Ax, Ah, br0, bz0, bxn0, bhn0,
                      hiK, hiP, h0own + rb * 2, hA + rb * 2);
        }
        {   // broadcast h0_new to all 4 CTAs (other buffer -> no race)
            uint32_t base = smem_u32(h0nxt);
#pragma unroll
            for (int v2 = 0; v2 < 4; ++v2) {
                int row = rowb + (v2 >> 1) * 8 + 2 * kq + (v2 & 1);
                uint32_t la = base + (uint32_t)(row * H_ + posu) * 4u;
#pragma unroll
                for (int rk = 0; rk < CL_; ++rk) st_cluster_f32(la, rk, hA[v2]);
            }
        }
        CLUSTER_SYNC();        // S1: h0(t) visible; x(t)/h0cur readers done

        // stage x(t+1) (protected by S1; readers resume after S3)
        if (t + 1 < T_) {
            int r = tid >> 3, q = tid & 7;
            int kqq = q / 3, kk = q - 3 * kqq;
            *(float4*)&xs[r * KX_ + kk * 16 + kqq * 4] =
                *(const float4*)(x + ((size_t)(b0 + r) * T_ + t + 1) * F_ + q * 4);
        }

        // ---------- layer 1 ----------
#pragma unroll
        for (int rb = 0; rb < 2; ++rb) {
            block_accum<8, H_>(sm + OFF_WIH1, sm + OFF_WHH1,
                               h0nxt + (rowb + rb * 8) * H_,
                               h1s + (rowb + rb * 8) * H_,
                               tb, kqo, Ar, Az, Ax, Ah);
            finalize2(Ar, Az, Ax, Ah, br1, bz1, bxn1, bhn1,
                      hiK, hiP, h1own + rb * 2, hA + rb * 2);
        }
        CLUSTER_SYNC();        // S2: everyone finished READING h1(t-1)
        {   // write h1(t) into the single buffer
            uint32_t base = smem_u32(h1s);
#pragma unroll
            for (int v2 = 0; v2 < 4; ++v2) {
                int row = rowb + (v2 >> 1) * 8 + 2 * kq + (v2 & 1);
                uint32_t la = base + (uint32_t)(row * H_ + posu) * 4u;
#pragma unroll
                for (int rk = 0; rk < CL_; ++rk) st_cluster_f32(la, rk, hA[v2]);
            }
        }
        CLUSTER_SYNC();        // S3: h1(t) visible
    }

    // ---------- head: rows [crank*8, crank*8+8) ----------
    float* scratch = xs;       // 1536 floats >= 8*128
    if (tid < H_) {
        const int uu = tid;
        const float w2  = head_w2[uu];
        const float b1v = head_b1[uu];
        float acc[8];
#pragma unroll
        for (int r = 0; r < 8; ++r) acc[r] = b1v;
#pragma unroll
        for (int kq4 = 0; kq4 < 4; ++kq4)
#pragma unroll
            for (int kk = 0; kk < 8; ++kk) {
                float4 w = *(const float4*)
                    (head_w1 + (size_t)uu * H_ + kq4 * 32 + kk * 4);
#pragma unroll
                for (int r = 0; r < 8; ++r) {
                    float4 v = *(const float4*)
                        &h1s[(crank * 8 + r) * H_ + kk * 16 + kq4 * 4];
                    acc[r] += w.x * v.x + w.y * v.y + w.z * v.z + w.w * v.w;
                }
            }
#pragma unroll
        for (int r = 0; r < 8; ++r)
            scratch[r * H_ + uu] = fmaxf(acc[r], 0.f) * w2;
    }
    __syncthreads();
    if (tid < 8) {
        float acc = head_b2[0];
        for (int k = 0; k < H_; ++k) acc += scratch[tid * H_ + k];
        y[b0 + crank * 8 + tid] = acc;
    }
}

extern "C" void kernel_launch(void* const* d_in, const int* in_sizes, int n_in,
                              void* d_out, int out_size) {
    const float* x       = (const float*)d_in[0];
    const int*   ticker  = (const int*)  d_in[1];
    const float* embed   = (const float*)d_in[2];
    const float* W_ih0   = (const float*)d_in[3];
    const float* W_hh0   = (const float*)d_in[4];
    const float* b_ih0   = (const float*)d_in[5];
    const float* b_hh0   = (const float*)d_in[6];
    const float* W_ih1   = (const float*)d_in[7];
    const float* W_hh1   = (const float*)d_in[8];
    const float* b_ih1   = (const float*)d_in[9];
    const float* b_hh1   = (const float*)d_in[10];
    const float* head_w1 = (const float*)d_in[11];
    const float* head_b1 = (const float*)d_in[12];
    const float* head_w2 = (const float*)d_in[13];
    const float* head_b2 = (const float*)d_in[14];

    cudaFuncSetAttribute(gru_kernel,
                         cudaFuncAttributeMaxDynamicSharedMemorySize, SMEM_BYTES);

    cudaLaunchConfig_t cfg = {};
    cfg.gridDim  = dim3(NCTA, 1, 1);
    cfg.blockDim = dim3(NTHR, 1, 1);
    cfg.dynamicSmemBytes = SMEM_BYTES;
    cfg.stream = 0;
    cudaLaunchAttribute attr[1];
    attr[0].id = cudaLaunchAttributeClusterDimension;
    attr[0].val.clusterDim.x = CL_;
    attr[0].val.clusterDim.y = 1;
    attr[0].val.clusterDim.z = 1;
    cfg.attrs = attr;
    cfg.numAttrs = 1;

    cudaLaunchKernelEx(&cfg, gru_kernel,
                       x, ticker, embed,
                       b_ih0, b_hh0, b_ih1, b_hh1,
                       head_w1, head_b1, head_w2, head_b2,
                       W_ih0, W_hh0, W_ih1, W_hh1,
                       (float*)d_out);
}

// round 8
// speedup vs baseline: 3.1439x; 1.0982x over previous
#include <cuda_runtime.h>
#include <cstdint>

#define T_    512
#define F_    32
#define E_    16
#define H_    128
#define KX_   48
#define CL_   4
#define UN_   32
#define RWS_  32
#define NCTA  128
#define NTHR  512   // tid = rq*128 + u*4 + kq

typedef unsigned long long u64;

// SMEM (floats). Weights: [kk][gate_type][u][kq][4] -> kk*1536 + gt*512 + u*16 + kq*4
#define OFF_WIH0 0
#define OFF_WHH0 (OFF_WIH0 + 3*1536)
#define OFF_WIH1 (OFF_WHH0 + 8*1536)
#define OFF_WHH1 (OFF_WIH1 + 8*1536)
#define OFF_H0   (OFF_WHH1 + 8*1536)          // 2 buffers
#define OFF_H1   (OFF_H0 + 2*RWS_*H_)         // single buffer
#define OFF_X    (OFF_H1 + RWS_*H_)           // single buffer
#define SMEM_FLOATS (OFF_X + RWS_*KX_)
#define SMEM_BYTES  (SMEM_FLOATS * 4)         // 221184

__device__ __forceinline__ u64 fma2(u64 a, u64 b, u64 c) {
    u64 d;
    asm("fma.rn.f32x2 %0, %1, %2, %3;" : "=l"(d) : "l"(a), "l"(b), "l"(c));
    return d;
}
__device__ __forceinline__ float hsum2(u64 a) {
    float l, h;
    asm("mov.b64 {%0, %1}, %2;" : "=f"(l), "=f"(h) : "l"(a));
    return l + h;
}
__device__ __forceinline__ float sigmoidf_(float v) {
    return 1.f / (1.f + __expf(-v));
}
__device__ __forceinline__ float tanhf_(float v) {
    v = fminf(fmaxf(v, -15.f), 15.f);
    float e = __expf(2.f * v);
    return (e - 1.f) / (e + 1.f);
}
__device__ __forceinline__ uint32_t smem_u32(const void* p) {
    uint32_t a;
    asm("{ .reg .u64 t; cvta.to.shared.u64 t, %1; cvt.u32.u64 %0, t; }"
        : "=r"(a) : "l"(p));
    return a;
}
__device__ __forceinline__ void st_cluster_f32(uint32_t laddr, int rank, float v) {
    asm volatile(
        "{ .reg .b32 ra;\n\t"
        "mapa.shared::cluster.u32 ra, %0, %1;\n\t"
        "st.shared::cluster.f32 [ra], %2; }"
        :: "r"(laddr), "r"(rank), "f"(v) : "memory");
}
#define CLUSTER_SYNC() do { \
    asm volatile("barrier.cluster.arrive.aligned;" ::: "memory"); \
    asm volatile("barrier.cluster.wait.aligned;"   ::: "memory"); \
} while (0)

// Accumulate one 8-row block: ih part (NIH quads, stride SIH) feeds r,z,xn;
// hh part (8 quads, stride H_) feeds r,z,hn.
template<int NIH, int SIH>
__device__ __forceinline__ void block_accum(
    const float* __restrict__ Wih, const float* __restrict__ Whh,
    const float* __restrict__ vih, const float* __restrict__ vhh,
    int tb, int kqo,
    u64* __restrict__ Ar, u64* __restrict__ Az,
    u64* __restrict__ Ax, u64* __restrict__ Ah)
{
#pragma unroll
    for (int r = 0; r < 8; ++r) { Ar[r] = 0; Az[r] = 0; Ax[r] = 0; Ah[r] = 0; }
#pragma unroll
    for (int kk = 0; kk < NIH; ++kk) {
        const float* wp = Wih + kk * 1536 + tb;
        ulonglong2 wr = *(const ulonglong2*)wp;
        ulonglong2 wz = *(const ulonglong2*)(wp + 512);
        ulonglong2 wn = *(const ulonglong2*)(wp + 1024);
#pragma unroll
        for (int r = 0; r < 8; ++r) {
            ulonglong2 v = *(const ulonglong2*)(vih + r * SIH + kk * 16 + kqo);
            Ar[r] = fma2(wr.x, v.x, Ar[r]); Ar[r] = fma2(wr.y, v.y, Ar[r]);
            Az[r] = fma2(wz.x, v.x, Az[r]); Az[r] = fma2(wz.y, v.y, Az[r]);
            Ax[r] = fma2(wn.x, v.x, Ax[r]); Ax[r] = fma2(wn.y, v.y, Ax[r]);
        }
    }
#pragma unroll
    for (int kk = 0; kk < 8; ++kk) {
        const float* wp = Whh + kk * 1536 + tb;
        ulonglong2 wr = *(const ulonglong2*)wp;
        ulonglong2 wz = *(const ulonglong2*)(wp + 512);
        ulonglong2 wn = *(const ulonglong2*)(wp + 1024);
#pragma unroll
        for (int r = 0; r < 8; ++r) {
            ulonglong2 v = *(const ulonglong2*)(vhh + r * H_ + kk * 16 + kqo);
            Ar[r] = fma2(wr.x, v.x, Ar[r]); Ar[r] = fma2(wr.y, v.y, Ar[r]);
            Az[r] = fma2(wz.x, v.x, Az[r]); Az[r] = fma2(wz.y, v.y, Az[r]);
            Ah[r] = fma2(wn.x, v.x, Ah[r]); Ah[r] = fma2(wn.y, v.y, Ah[r]);
        }
    }
}

#define RED4(kout, s) \
    _Pragma("unroll") \
    for (int rr = 0; rr < 4; ++rr) { \
        float snd = hiK ? (s)[rr] : (s)[4 + rr]; \
        float kp  = hiK ? (s)[4 + rr] : (s)[rr]; \
        (kout)[rr] = kp + __shfl_xor_sync(0xffffffffu, snd, 2, 4); }
#define RED2(f, kin, rr) { \
        float snd = hiP ? (kin)[rr] : (kin)[2 + rr]; \
        float kp  = hiP ? (kin)[2 + rr] : (kin)[rr]; \
        f = kp + __shfl_xor_sync(0xffffffffu, snd, 1, 4); }

// Cross-kq reduce over the thread's 8 rows; lane kq finalizes rows 2kq, 2kq+1.
__device__ __forceinline__ void finalize2(
    const u64* Ar, const u64* Az, const u64* Ax, const u64* Ah,
    float br, float bz, float bxn, float bhn,
    bool hiK, bool hiP, float* hown, float* hout)
{
    float sr[8], sz[8], sx[8], sh[8];
#pragma unroll
    for (int r = 0; r < 8; ++r) {
        sr[r] = hsum2(Ar[r]); sz[r] = hsum2(Az[r]);
        sx[r] = hsum2(Ax[r]); sh[r] = hsum2(Ah[r]);
    }
    float kr[4], kz[4], kx[4], kh[4];
    RED4(kr, sr); RED4(kz, sz); RED4(kx, sx); RED4(kh, sh);
#pragma unroll
    for (int rr = 0; rr < 2; ++rr) {
        float fr, fz, fx, fh;
        RED2(fr, kr, rr); RED2(fz, kz, rr); RED2(fx, kx, rr); RED2(fh, kh, rr);
        float R = sigmoidf_(fr + br);
        float Z = sigmoidf_(fz + bz);
        float N = tanhf_(fx + bxn + R * (fh + bhn));
        float h = N + Z * (hown[rr] - N);
        hown[rr] = h;
        hout[rr] = h;
    }
}

__global__ void __launch_bounds__(NTHR, 1) gru_kernel(
    const float* __restrict__ x,
    const int*   __restrict__ ticker,
    const float* __restrict__ embed,
    const float* __restrict__ b_ih0, const float* __restrict__ b_hh0,
    const float* __restrict__ b_ih1, const float* __restrict__ b_hh1,
    const float* __restrict__ head_w1, const float* __restrict__ head_b1,
    const float* __restrict__ head_w2, const float* __restrict__ head_b2,
    const float* __restrict__ W_ih0, const float* __restrict__ W_hh0,
    const float* __restrict__ W_ih1, const float* __restrict__ W_hh1,
    float* __restrict__ y)
{
    extern __shared__ __align__(16) float sm[];
    const int tid   = threadIdx.x;
    const int kq    = tid & 3;
    const int u     = (tid >> 2) & 31;        // local unit
    const int rq    = tid >> 7;               // row quarter 0..3
    const int crank = blockIdx.x & 3;
    const int b0    = (blockIdx.x >> 2) * RWS_;

    const int  tb   = u * 16 + kq * 4;        // weight thread base
    const int  kqo  = kq * 4;                 // operand kq offset
    const bool hiK  = kq & 2, hiP = kq & 1;
    const int  posu = (u >> 2) * 16 + crank * 4 + (u & 3);
    const int  rowb = rq * 8;                 // this thread's 8-row block

    // ---- one-time weight remap into SMEM ----
    for (int idx = tid; idx < 96 * KX_; idx += NTHR) {
        int g = idx / KX_, k = idx % KX_;
        int gt = g / 32, uu = g & 31;
        int kqq = k / 12, kk = (k % 12) >> 2, i = k & 3;
        sm[OFF_WIH0 + kk * 1536 + gt * 512 + uu * 16 + kqq * 4 + i] =
            W_ih0[(size_t)(gt * H_ + crank * UN_ + uu) * KX_ + k];
    }
    for (int idx = tid; idx < 96 * H_; idx += NTHR) {
        int g = idx / H_, k = idx % H_;
        int gt = g / 32, uu = g & 31;
        int kqq = k >> 5, kk = (k & 31) >> 2, i = k & 3;
        int dst = kk * 1536 + gt * 512 + uu * 16 + kqq * 4 + i;
        size_t grow = (size_t)(gt * H_ + crank * UN_ + uu);
        sm[OFF_WHH0 + dst] = W_hh0[grow * H_ + k];
        sm[OFF_WIH1 + dst] = W_ih1[grow * H_ + k];
        sm[OFF_WHH1 + dst] = W_hh1[grow * H_ + k];
    }
    for (int i = tid; i < 2 * RWS_ * H_; i += NTHR) sm[OFF_H0 + i] = 0.f;
    for (int i = tid; i < RWS_ * H_; i += NTHR)     sm[OFF_H1 + i] = 0.f;
    // embedding (constant, pos-mapped; never overwritten by x staging)
    for (int idx = tid; idx < RWS_ * E_; idx += NTHR) {
        int r = idx >> 4, e = idx & 15, k = F_ + e;
        int kqq = k / 12, kk = (k % 12) >> 2, i = k & 3;
        sm[OFF_X + r * KX_ + kk * 16 + kqq * 4 + i] =
            embed[(size_t)ticker[b0 + r] * E_ + e];
    }
    // x(t=0), pos-mapped (256 slots)
    if (tid < 256) {
        int r = tid >> 3, q = tid & 7;
        int kqq = q / 3, kk = q - 3 * kqq;
        *(float4*)&sm[OFF_X + r * KX_ + kk * 16 + kqq * 4] =
            *(const float4*)(x + ((size_t)(b0 + r) * T_) * F_ + q * 4);
    }
    // biases for my unit
    const int jr = crank * UN_ + u;
    const float br0  = b_ih0[jr] + b_hh0[jr];
    const float bz0  = b_ih0[H_ + jr] + b_hh0[H_ + jr];
    const float bxn0 = b_ih0[2 * H_ + jr], bhn0 = b_hh0[2 * H_ + jr];
    const float br1  = b_ih1[jr] + b_hh1[jr];
    const float bz1  = b_ih1[H_ + jr] + b_hh1[H_ + jr];
    const float bxn1 = b_ih1[2 * H_ + jr], bhn1 = b_hh1[2 * H_ + jr];

    float h0own[2] = {0.f, 0.f};
    float h1own[2] = {0.f, 0.f};

    __syncthreads();
    CLUSTER_SYNC();

    float* xs  = sm + OFF_X;
    float* h1s = sm + OFF_H1;

    for (int t = 0; t < T_; ++t) {
        const float* h0cur = sm + OFF_H0 + (t & 1) * RWS_ * H_;
        float*       h0nxt = sm + OFF_H0 + ((t + 1) & 1) * RWS_ * H_;
        u64 Ar[8], Az[8], Ax[8], Ah[8];
        float hA[2];

        // ---------- layer 0 ----------
        block_accum<3, KX_>(sm + OFF_WIH0, sm + OFF_WHH0,
                            xs + rowb * KX_, h0cur + rowb * H_,
                            tb, kqo, Ar, Az, Ax, Ah);
        finalize2(Ar, Az, Ax, Ah, br0, bz0, bxn0, bhn0,
                  hiK, hiP, h0own, hA);
        {   // broadcast h0_new to all 4 CTAs (other buffer -> no race)
            uint32_t base = smem_u32(h0nxt);
#pragma unroll
            for (int v2 = 0; v2 < 2; ++v2) {
                int row = rowb + 2 * kq + v2;
                uint32_t la = base + (uint32_t)(row * H_ + posu) * 4u;
#pragma unroll
                for (int rk = 0; rk < CL_; ++rk) st_cluster_f32(la, rk, hA[v2]);
            }
        }
        CLUSTER_SYNC();        // S1: h0(t) visible; x(t)/h0cur readers done

        // stage x(t+1) (protected by S1; readers resume after S3)
        if (t + 1 < T_ && tid < 256) {
            int r = tid >> 3, q = tid & 7;
            int kqq = q / 3, kk = q - 3 * kqq;
            *(float4*)&xs[r * KX_ + kk * 16 + kqq * 4] =
                *(const float4*)(x + ((size_t)(b0 + r) * T_ + t + 1) * F_ + q * 4);
        }

        // ---------- layer 1 ----------
        block_accum<8, H_>(sm + OFF_WIH1, sm + OFF_WHH1,
                           h0nxt + rowb * H_, h1s + rowb * H_,
                           tb, kqo, Ar, Az, Ax, Ah);
        finalize2(Ar, Az, Ax, Ah, br1, bz1, bxn1, bhn1,
                  hiK, hiP, h1own, hA);
        CLUSTER_SYNC();        // S2: everyone finished READING h1(t-1)
        {   // write h1(t) into the single buffer
            uint32_t base = smem_u32(h1s);
#pragma unroll
            for (int v2 = 0; v2 < 2; ++v2) {
                int row = rowb + 2 * kq + v2;
                uint32_t la = base + (uint32_t)(row * H_ + posu) * 4u;
#pragma unroll
                for (int rk = 0; rk < CL_; ++rk) st_cluster_f32(la, rk, hA[v2]);
            }
        }
        CLUSTER_SYNC();        // S3: h1(t) visible
    }

    // ---------- head: rows [crank*8, crank*8+8) ----------
    float* scratch = xs;       // 1536 floats >= 8*128
    if (tid < H_) {
        const int uu = tid;
        const float w2  = head_w2[uu];
        const float b1v = head_b1[uu];
        float acc[8];
#pragma unroll
        for (int r = 0; r < 8; ++r) acc[r] = b1v;
#pragma unroll
        for (int kq4 = 0; kq4 < 4; ++kq4)
#pragma unroll
            for (int kk = 0; kk < 8; ++kk) {
                float4 w = *(const float4*)
                    (head_w1 + (size_t)uu * H_ + kq4 * 32 + kk * 4);
#pragma unroll
                for (int r = 0; r < 8; ++r) {
                    float4 v = *(const float4*)
                        &h1s[(crank * 8 + r) * H_ + kk * 16 + kq4 * 4];
                    acc[r] += w.x * v.x + w.y * v.y + w.z * v.z + w.w * v.w;
                }
            }
#pragma unroll
        for (int r = 0; r < 8; ++r)
            scratch[r * H_ + uu] = fmaxf(acc[r], 0.f) * w2;
    }
    __syncthreads();
    if (tid < 8) {
        float acc = head_b2[0];
        for (int k = 0; k < H_; ++k) acc += scratch[tid * H_ + k];
        y[b0 + crank * 8 + tid] = acc;
    }
}

extern "C" void kernel_launch(void* const* d_in, const int* in_sizes, int n_in,
                              void* d_out, int out_size) {
    const float* x       = (const float*)d_in[0];
    const int*   ticker  = (const int*)  d_in[1];
    const float* embed   = (const float*)d_in[2];
    const float* W_ih0   = (const float*)d_in[3];
    const float* W_hh0   = (const float*)d_in[4];
    const float* b_ih0   = (const float*)d_in[5];
    const float* b_hh0   = (const float*)d_in[6];
    const float* W_ih1   = (const float*)d_in[7];
    const float* W_hh1   = (const float*)d_in[8];
    const float* b_ih1   = (const float*)d_in[9];
    const float* b_hh1   = (const float*)d_in[10];
    const float* head_w1 = (const float*)d_in[11];
    const float* head_b1 = (const float*)d_in[12];
    const float* head_w2 = (const float*)d_in[13];
    const float* head_b2 = (const float*)d_in[14];

    cudaFuncSetAttribute(gru_kernel,
                         cudaFuncAttributeMaxDynamicSharedMemorySize, SMEM_BYTES);

    cudaLaunchConfig_t cfg = {};
    cfg.gridDim  = dim3(NCTA, 1, 1);
    cfg.blockDim = dim3(NTHR, 1, 1);
    cfg.dynamicSmemBytes = SMEM_BYTES;
    cfg.stream = 0;
    cudaLaunchAttribute attr[1];
    attr[0].id = cudaLaunchAttributeClusterDimension;
    attr[0].val.clusterDim.x = CL_;
    attr[0].val.clusterDim.y = 1;
    attr[0].val.clusterDim.z = 1;
    cfg.attrs = attr;
    cfg.numAttrs = 1;

    cudaLaunchKernelEx(&cfg, gru_kernel,
                       x, ticker, embed,
                       b_ih0, b_hh0, b_ih1, b_hh1,
                       head_w1, head_b1, head_w2, head_b2,
                       W_ih0, W_hh0, W_ih1, W_hh1,
                       (float*)d_out);
}